// round 1
// baseline (speedup 1.0000x reference)
#include <cuda_runtime.h>
#include <math.h>

// Problem constants (from reference): N=100000, L=48, E=1600000, ED=17, H=48
#define NN 100000
#define LL 48
#define EE 1600000
#define EDD 17
#define CAP (1<<18)

// Scratch (static __device__ globals: allowed; no runtime allocation)
__device__ float g_x[NN*LL];       // x_t for flagged nodes (t>=1)
__device__ float g_v[NN*LL];       // v_t for flagged nodes (t>=1)
__device__ float g_agg[NN*LL];     // per-iteration aggregation
__device__ float g_wbase[EE];      // per-edge constant w_base = g@Ww+bw (filled for list1 edges)
__device__ unsigned char g_flag1[NN];
__device__ unsigned char g_flag2[NN];
__device__ int g_list1[CAP];
__device__ int g_list2[CAP];
__device__ int g_list3[CAP];
__device__ int g_cnt[4];

__device__ __forceinline__ float geluf(float x) {
    // exact gelu: x * 0.5 * (1 + erf(x / sqrt(2)))
    return 0.5f * x * (1.0f + erff(x * 0.70710678118654752f));
}
__device__ __forceinline__ float sigm(float x) {
    return 1.0f / (1.0f + expf(-x));
}

// ---------------------------------------------------------------------------
// Init: clear flags + counters (x/v are computed lazily from nodes*valid)
// ---------------------------------------------------------------------------
__global__ void k_init(int n) {
    int i = blockIdx.x * blockDim.x + threadIdx.x;
    if (i < n) {
        g_flag1[i] = (i == 0) ? 1 : 0;
        g_flag2[i] = (i == 0) ? 1 : 0;
    }
    if (i < 4) g_cnt[i] = 0;
}

// ---------------------------------------------------------------------------
// Frontier scans (must run sequentially: l3 -> l2 -> l1)
// list3: edges into node 0 (used at iteration 3); marks flag2 (and flag1)
// list2: edges into flag2 nodes (iteration 2); marks flag1
// list1: edges into flag1 nodes (iteration 1)
// ---------------------------------------------------------------------------
__global__ void k_scan_l3(const int* __restrict__ src, const int* __restrict__ dst, int e) {
    int i = blockIdx.x * blockDim.x + threadIdx.x;
    if (i >= e) return;
    if (dst[i] == 0) {
        int p = atomicAdd(&g_cnt[3], 1);
        if (p < CAP) g_list3[p] = i;
        int s = src[i];
        g_flag2[s] = 1;
        g_flag1[s] = 1;
    }
}
__global__ void k_scan_l2(const int* __restrict__ src, const int* __restrict__ dst, int e) {
    int i = blockIdx.x * blockDim.x + threadIdx.x;
    if (i >= e) return;
    if (g_flag2[dst[i]]) {
        int p = atomicAdd(&g_cnt[2], 1);
        if (p < CAP) g_list2[p] = i;
        g_flag1[src[i]] = 1;
    }
}
__global__ void k_scan_l1(const int* __restrict__ src, const int* __restrict__ dst, int e) {
    int i = blockIdx.x * blockDim.x + threadIdx.x;
    if (i >= e) return;
    if (g_flag1[dst[i]]) {
        int p = atomicAdd(&g_cnt[1], 1);
        if (p < CAP) g_list1[p] = i;
    }
}

// ---------------------------------------------------------------------------
// Per-edge constant: w_base = gelu(relu(gelu(ea@W1+b1)@W2+b2)@Wg+bg)@Ww + bw
// warp per edge; lane j owns outputs j and j+32 (j<16); shuffle-broadcast
// hidden activations for the 48x48 layers.
// ---------------------------------------------------------------------------
__global__ void k_wbase(const float* __restrict__ ea_all,
                        const float* __restrict__ W1, const float* __restrict__ b1,
                        const float* __restrict__ W2, const float* __restrict__ b2,
                        const float* __restrict__ Wg, const float* __restrict__ bg,
                        const float* __restrict__ Ww, const float* __restrict__ bw) {
    int lane  = threadIdx.x & 31;
    int warp  = (blockIdx.x * blockDim.x + threadIdx.x) >> 5;
    int nwarp = (gridDim.x * blockDim.x) >> 5;
    int cnt = min(g_cnt[1], CAP);
    bool lo = (lane < 16);

    for (int it = warp; it < cnt; it += nwarp) {
        int e = g_list1[it];
        const float* ea = ea_all + (long long)e * EDD;

        float a  = b1[lane];
        float a2 = lo ? b1[lane + 32] : 0.f;
        #pragma unroll
        for (int k = 0; k < EDD; k++) {
            float ev = ea[k];
            a = fmaf(ev, W1[k * 48 + lane], a);
            if (lo) a2 = fmaf(ev, W1[k * 48 + lane + 32], a2);
        }
        a = geluf(a); a2 = geluf(a2);

        float c  = b2[lane];
        float c2 = lo ? b2[lane + 32] : 0.f;
        #pragma unroll
        for (int k = 0; k < 48; k++) {
            float hk = (k < 32) ? __shfl_sync(0xffffffffu, a, k)
                                : __shfl_sync(0xffffffffu, a2, k - 32);
            c = fmaf(hk, W2[k * 48 + lane], c);
            if (lo) c2 = fmaf(hk, W2[k * 48 + lane + 32], c2);
        }
        c = fmaxf(c, 0.f); c2 = fmaxf(c2, 0.f);   // relu

        float d1 = bg[lane];
        float d2 = lo ? bg[lane + 32] : 0.f;
        #pragma unroll
        for (int k = 0; k < 48; k++) {
            float hk = (k < 32) ? __shfl_sync(0xffffffffu, c, k)
                                : __shfl_sync(0xffffffffu, c2, k - 32);
            d1 = fmaf(hk, Wg[k * 48 + lane], d1);
            if (lo) d2 = fmaf(hk, Wg[k * 48 + lane + 32], d2);
        }
        d1 = geluf(d1); d2 = geluf(d2);

        float p = d1 * Ww[lane] + (lo ? d2 * Ww[lane + 32] : 0.f);
        #pragma unroll
        for (int off = 16; off; off >>= 1) p += __shfl_xor_sync(0xffffffffu, p, off);
        if (lane == 0) g_wbase[e] = p + bw[0];
    }
}

// ---------------------------------------------------------------------------
// Zero agg for the nodes this iteration will update
// ---------------------------------------------------------------------------
__global__ void k_zero_agg(int level, int total) {
    int i = blockIdx.x * blockDim.x + threadIdx.x;
    if (i >= total) return;
    int u = i / LL;
    bool sel = (level == 1) ? (g_flag1[u] != 0)
             : (level == 2) ? (g_flag2[u] != 0)
                            : (u == 0);
    if (sel) g_agg[i] = 0.f;
}

// ---------------------------------------------------------------------------
// Aggregate messages for edges of this iteration's list.
// msg[:, :L] = x[src] * sigmoid(mean(v[src]) * w_base[e])  -> atomicAdd into agg[dst]
// Level 1 reads x_0/v_0 on the fly from nodes*valid / valid.
// ---------------------------------------------------------------------------
__global__ void k_agg(const int* __restrict__ src, const int* __restrict__ dst,
                      const float* __restrict__ nodes, const float* __restrict__ valid,
                      int level) {
    int lane  = threadIdx.x & 31;
    int warp  = (blockIdx.x * blockDim.x + threadIdx.x) >> 5;
    int nwarp = (gridDim.x * blockDim.x) >> 5;
    const int* list = (level == 1) ? g_list1 : (level == 2) ? g_list2 : g_list3;
    int cnt = min(g_cnt[level], CAP);
    bool lo = (lane < 16);

    for (int it = warp; it < cnt; it += nwarp) {
        int e = list[it];
        int s = src[e];
        int d = dst[e];
        long long sb = (long long)s * LL;

        float v0, v1, x0, x1;
        if (level == 1) {
            v0 = valid[sb + lane];
            v1 = lo ? valid[sb + lane + 32] : 0.f;
            x0 = nodes[sb + lane] * v0;
            x1 = lo ? nodes[sb + lane + 32] * v1 : 0.f;
        } else {
            v0 = g_v[sb + lane];
            v1 = lo ? g_v[sb + lane + 32] : 0.f;
            x0 = g_x[sb + lane];
            x1 = lo ? g_x[sb + lane + 32] : 0.f;
        }

        float sv = v0 + v1;
        #pragma unroll
        for (int off = 16; off; off >>= 1) sv += __shfl_xor_sync(0xffffffffu, sv, off);
        float sg = sigm((sv * (1.0f / 48.0f)) * g_wbase[e]);

        float* ad = g_agg + (long long)d * LL;
        atomicAdd(&ad[lane], x0 * sg);
        if (lo) atomicAdd(&ad[lane + 32], x1 * sg);
    }
}

// ---------------------------------------------------------------------------
// Node update for flagged nodes:
// m  = sigmoid(nh*Wf0 + x*Wf1 + nv*Wf2 + bf)
// x' = (1-m)*x + nv*m*nh
// v' = (l != 0) && (orig != x' || v > 0)
// orig = nodes*valid (recomputed; avoids a 19MB persistent copy)
// ---------------------------------------------------------------------------
__global__ void k_update(const float* __restrict__ nodes, const float* __restrict__ valid,
                         const float* __restrict__ Wf, const float* __restrict__ bf,
                         int level, int total) {
    int i = blockIdx.x * blockDim.x + threadIdx.x;
    if (i >= total) return;
    int u = i / LL;
    int l = i - u * LL;
    bool sel = (level == 1) ? (g_flag1[u] != 0)
             : (level == 2) ? (g_flag2[u] != 0)
                            : (u == 0);
    if (!sel) return;

    float orig = nodes[i] * valid[i];
    float xo, vo;
    if (level == 1) { xo = orig; vo = valid[i]; }
    else            { xo = g_x[i]; vo = g_v[i]; }

    float nh = g_agg[i];
    float nv = 1.0f - vo;
    float m  = sigm(nh * Wf[0] + xo * Wf[1] + nv * Wf[2] + bf[0]);
    float xn = (1.0f - m) * xo + nv * m * nh;
    float vn = (l != 0 && (orig != xn || vo > 0.0f)) ? 1.0f : 0.0f;
    g_x[i] = xn;
    g_v[i] = vn;
}

// ---------------------------------------------------------------------------
// Output: x[0][0:48]
// ---------------------------------------------------------------------------
__global__ void k_out(float* __restrict__ out) {
    int i = threadIdx.x;
    if (i < LL) out[i] = g_x[i];
}

extern "C" void kernel_launch(void* const* d_in, const int* in_sizes, int n_in,
                              void* d_out, int out_size) {
    const float* nodes     = (const float*)d_in[0];
    const int*   ei        = (const int*)d_in[1];
    const float* edge_attr = (const float*)d_in[2];
    const float* valid     = (const float*)d_in[3];
    // d_in[4]=r, d_in[5]=fx (unused)
    const float* W1 = (const float*)d_in[6];
    const float* b1 = (const float*)d_in[7];
    const float* W2 = (const float*)d_in[8];
    const float* b2 = (const float*)d_in[9];
    const float* Wg = (const float*)d_in[10];
    const float* bg = (const float*)d_in[11];
    const float* Ww = (const float*)d_in[12];
    const float* bw = (const float*)d_in[13];
    const float* Wf = (const float*)d_in[14];
    const float* bf = (const float*)d_in[15];

    int n = in_sizes[0] / LL;       // nodes: (N, L, 1)
    int e = in_sizes[1] / 2;        // edge_index: (2, E)
    const int* src = ei;
    const int* dst = ei + e;
    int total = n * LL;
    const int tb = 256;

    k_init<<<(n + tb - 1) / tb, tb>>>(n);
    k_scan_l3<<<(e + tb - 1) / tb, tb>>>(src, dst, e);
    k_scan_l2<<<(e + tb - 1) / tb, tb>>>(src, dst, e);
    k_scan_l1<<<(e + tb - 1) / tb, tb>>>(src, dst, e);
    k_wbase<<<256, 256>>>(edge_attr, W1, b1, W2, b2, Wg, bg, Ww, bw);

    for (int lvl = 1; lvl <= 3; lvl++) {
        k_zero_agg<<<(total + tb - 1) / tb, tb>>>(lvl, total);
        k_agg<<<256, 256>>>(src, dst, nodes, valid, lvl);
        k_update<<<(total + tb - 1) / tb, tb>>>(nodes, valid, Wf, bf, lvl, total);
    }
    k_out<<<1, 64>>>((float*)d_out);
}

// round 3
// speedup vs baseline: 1.8342x; 1.8342x over previous
#include <cuda_runtime.h>
#include <math.h>

// Problem constants: N=100000, L=48, E=1600000, ED=17, H=48
#define NN 100000
#define LL 48
#define EE 1600000
#define EDD 17
#define CAP (1<<18)
#define NCAP (1<<16)

__device__ float g_x[NN*LL];
__device__ float g_v[NN*LL];
__device__ float g_agg[NN*LL];
__device__ float g_wbase[EE];
__device__ unsigned int g_flag1[NN];
__device__ unsigned int g_flag2[NN];
__device__ int g_list1[CAP];
__device__ int g_list2[CAP];
__device__ int g_list3[CAP];
__device__ int g_nlist1[NCAP];
__device__ int g_nlist2[NCAP];
__device__ int g_nlist3[4];
__device__ int g_cnt[4];    // edge-list counters (index 1..3)
__device__ int g_ncnt[4];   // node-list counters (index 1..2)

__device__ __forceinline__ float geluf(float x) {
    return 0.5f * x * (1.0f + erff(x * 0.70710678118654752f));
}
__device__ __forceinline__ float sigm(float x) {
    return 1.0f / (1.0f + expf(-x));
}

// ---------------------------------------------------------------------------
// Init: clear flags + counters, seed node 0 into both node sets
// ---------------------------------------------------------------------------
__global__ void k_init(int n) {
    int i = blockIdx.x * blockDim.x + threadIdx.x;
    if (i < n) {
        g_flag1[i] = (i == 0) ? 1u : 0u;
        g_flag2[i] = (i == 0) ? 1u : 0u;
    }
    if (i == 0) {
        g_cnt[0] = g_cnt[1] = g_cnt[2] = g_cnt[3] = 0;
        g_nlist1[0] = 0; g_nlist2[0] = 0; g_nlist3[0] = 0;
        g_ncnt[1] = 1; g_ncnt[2] = 1;
    }
}

// ---------------------------------------------------------------------------
// Scans: 8 edges per thread via 2x int4 loads of dst
// ---------------------------------------------------------------------------
__global__ void k_scan_l3(const int* __restrict__ src, const int* __restrict__ dst, int e) {
    long long base = (long long)(blockIdx.x * blockDim.x + threadIdx.x) * 8;
    if (base >= e) return;
    int d[8];
    if (base + 8 <= e) {
        int4 a = __ldg((const int4*)(dst + base));
        int4 b = __ldg((const int4*)(dst + base + 4));
        d[0]=a.x; d[1]=a.y; d[2]=a.z; d[3]=a.w;
        d[4]=b.x; d[5]=b.y; d[6]=b.z; d[7]=b.w;
    } else {
        #pragma unroll
        for (int t = 0; t < 8; t++) d[t] = (base + t < e) ? dst[base + t] : -1;
    }
    #pragma unroll
    for (int t = 0; t < 8; t++) {
        if (d[t] == 0) {
            int i = (int)base + t;
            int p = atomicAdd(&g_cnt[3], 1);
            if (p < CAP) g_list3[p] = i;
            int s = src[i];
            if (atomicExch(&g_flag2[s], 1u) == 0u) {
                int q = atomicAdd(&g_ncnt[2], 1);
                if (q < NCAP) g_nlist2[q] = s;
            }
            if (atomicExch(&g_flag1[s], 1u) == 0u) {
                int q = atomicAdd(&g_ncnt[1], 1);
                if (q < NCAP) g_nlist1[q] = s;
            }
        }
    }
}

__global__ void k_scan_l2(const int* __restrict__ src, const int* __restrict__ dst, int e) {
    long long base = (long long)(blockIdx.x * blockDim.x + threadIdx.x) * 8;
    if (base >= e) return;
    int d[8];
    if (base + 8 <= e) {
        int4 a = __ldg((const int4*)(dst + base));
        int4 b = __ldg((const int4*)(dst + base + 4));
        d[0]=a.x; d[1]=a.y; d[2]=a.z; d[3]=a.w;
        d[4]=b.x; d[5]=b.y; d[6]=b.z; d[7]=b.w;
    } else {
        #pragma unroll
        for (int t = 0; t < 8; t++) d[t] = (base + t < e) ? dst[base + t] : -1;
    }
    unsigned int f[8];
    #pragma unroll
    for (int t = 0; t < 8; t++) f[t] = (d[t] >= 0) ? __ldg(&g_flag2[d[t]]) : 0u;
    #pragma unroll
    for (int t = 0; t < 8; t++) {
        if (f[t]) {
            int i = (int)base + t;
            int p = atomicAdd(&g_cnt[2], 1);
            if (p < CAP) g_list2[p] = i;
            int s = src[i];
            if (atomicExch(&g_flag1[s], 1u) == 0u) {
                int q = atomicAdd(&g_ncnt[1], 1);
                if (q < NCAP) g_nlist1[q] = s;
            }
        }
    }
}

__global__ void k_scan_l1(const int* __restrict__ dst, int e) {
    long long base = (long long)(blockIdx.x * blockDim.x + threadIdx.x) * 8;
    if (base >= e) return;
    int d[8];
    if (base + 8 <= e) {
        int4 a = __ldg((const int4*)(dst + base));
        int4 b = __ldg((const int4*)(dst + base + 4));
        d[0]=a.x; d[1]=a.y; d[2]=a.z; d[3]=a.w;
        d[4]=b.x; d[5]=b.y; d[6]=b.z; d[7]=b.w;
    } else {
        #pragma unroll
        for (int t = 0; t < 8; t++) d[t] = (base + t < e) ? dst[base + t] : -1;
    }
    unsigned int f[8];
    #pragma unroll
    for (int t = 0; t < 8; t++) f[t] = (d[t] >= 0) ? __ldg(&g_flag1[d[t]]) : 0u;
    #pragma unroll
    for (int t = 0; t < 8; t++) {
        if (f[t]) {
            int p = atomicAdd(&g_cnt[1], 1);
            if (p < CAP) g_list1[p] = (int)base + t;
        }
    }
}

// ---------------------------------------------------------------------------
// Zero agg for level-1 nodes (later levels re-zeroed inside k_update)
// ---------------------------------------------------------------------------
__global__ void k_zero1() {
    int total = min(g_ncnt[1], NCAP) * LL;
    for (int q = blockIdx.x * blockDim.x + threadIdx.x; q < total;
         q += gridDim.x * blockDim.x) {
        int u = g_nlist1[q / LL];
        g_agg[(long long)u * LL + (q % LL)] = 0.f;
    }
}

// ---------------------------------------------------------------------------
// Per-edge constant: w_base = gelu(relu(gelu(ea@W1+b1)@W2+b2)@Wg+bg)@Ww + bw
// ---------------------------------------------------------------------------
__global__ void k_wbase(const float* __restrict__ ea_all,
                        const float* __restrict__ W1, const float* __restrict__ b1,
                        const float* __restrict__ W2, const float* __restrict__ b2,
                        const float* __restrict__ Wg, const float* __restrict__ bg,
                        const float* __restrict__ Ww, const float* __restrict__ bw) {
    int lane  = threadIdx.x & 31;
    int warp  = (blockIdx.x * blockDim.x + threadIdx.x) >> 5;
    int nwarp = (gridDim.x * blockDim.x) >> 5;
    int cnt = min(g_cnt[1], CAP);
    bool lo = (lane < 16);

    for (int it = warp; it < cnt; it += nwarp) {
        int e = g_list1[it];
        const float* ea = ea_all + (long long)e * EDD;

        float a  = b1[lane];
        float a2 = lo ? b1[lane + 32] : 0.f;
        #pragma unroll
        for (int k = 0; k < EDD; k++) {
            float ev = __ldg(&ea[k]);
            a = fmaf(ev, W1[k * 48 + lane], a);
            if (lo) a2 = fmaf(ev, W1[k * 48 + lane + 32], a2);
        }
        a = geluf(a); a2 = geluf(a2);

        float c  = b2[lane];
        float c2 = lo ? b2[lane + 32] : 0.f;
        #pragma unroll
        for (int k = 0; k < 48; k++) {
            float hk = (k < 32) ? __shfl_sync(0xffffffffu, a, k)
                                : __shfl_sync(0xffffffffu, a2, k - 32);
            c = fmaf(hk, W2[k * 48 + lane], c);
            if (lo) c2 = fmaf(hk, W2[k * 48 + lane + 32], c2);
        }
        c = fmaxf(c, 0.f); c2 = fmaxf(c2, 0.f);

        float d1 = bg[lane];
        float d2 = lo ? bg[lane + 32] : 0.f;
        #pragma unroll
        for (int k = 0; k < 48; k++) {
            float hk = (k < 32) ? __shfl_sync(0xffffffffu, c, k)
                                : __shfl_sync(0xffffffffu, c2, k - 32);
            d1 = fmaf(hk, Wg[k * 48 + lane], d1);
            if (lo) d2 = fmaf(hk, Wg[k * 48 + lane + 32], d2);
        }
        d1 = geluf(d1); d2 = geluf(d2);

        float p = d1 * Ww[lane] + (lo ? d2 * Ww[lane + 32] : 0.f);
        #pragma unroll
        for (int off = 16; off; off >>= 1) p += __shfl_xor_sync(0xffffffffu, p, off);
        if (lane == 0) g_wbase[e] = p + bw[0];
    }
}

// ---------------------------------------------------------------------------
// Aggregate: warp per edge, atomicAdd into agg[dst]
// ---------------------------------------------------------------------------
__global__ void k_agg(const int* __restrict__ src, const int* __restrict__ dst,
                      const float* __restrict__ nodes, const float* __restrict__ valid,
                      int level) {
    int lane  = threadIdx.x & 31;
    int warp  = (blockIdx.x * blockDim.x + threadIdx.x) >> 5;
    int nwarp = (gridDim.x * blockDim.x) >> 5;
    const int* list = (level == 1) ? g_list1 : (level == 2) ? g_list2 : g_list3;
    int cnt = min(g_cnt[level], CAP);
    bool lo = (lane < 16);

    for (int it = warp; it < cnt; it += nwarp) {
        int e = list[it];
        int s = __ldg(&src[e]);
        int d = __ldg(&dst[e]);
        long long sb = (long long)s * LL;

        float v0, v1, x0, x1;
        if (level == 1) {
            v0 = __ldg(&valid[sb + lane]);
            v1 = lo ? __ldg(&valid[sb + lane + 32]) : 0.f;
            x0 = __ldg(&nodes[sb + lane]) * v0;
            x1 = lo ? __ldg(&nodes[sb + lane + 32]) * v1 : 0.f;
        } else {
            v0 = g_v[sb + lane];
            v1 = lo ? g_v[sb + lane + 32] : 0.f;
            x0 = g_x[sb + lane];
            x1 = lo ? g_x[sb + lane + 32] : 0.f;
        }

        float sv = v0 + v1;
        #pragma unroll
        for (int off = 16; off; off >>= 1) sv += __shfl_xor_sync(0xffffffffu, sv, off);
        float sg = sigm((sv * (1.0f / 48.0f)) * g_wbase[e]);

        float* ad = g_agg + (long long)d * LL;
        atomicAdd(&ad[lane], x0 * sg);
        if (lo) atomicAdd(&ad[lane + 32], x1 * sg);
    }
}

// ---------------------------------------------------------------------------
// Node update over the level's compact node list.
// Also re-zeroes g_agg (covers next level since flag_{l+1} subset flag_l),
// and at level 3 writes the final output for node 0.
// ---------------------------------------------------------------------------
__global__ void k_update(const float* __restrict__ nodes, const float* __restrict__ valid,
                         const float* __restrict__ Wf, const float* __restrict__ bf,
                         int level, float* __restrict__ out) {
    const int* nlist = (level == 1) ? g_nlist1 : (level == 2) ? g_nlist2 : g_nlist3;
    int cnt = (level == 3) ? 1 : min(g_ncnt[level], NCAP);
    int total = cnt * LL;
    float wf0 = Wf[0], wf1 = Wf[1], wf2 = Wf[2], b0 = bf[0];

    for (int q = blockIdx.x * blockDim.x + threadIdx.x; q < total;
         q += gridDim.x * blockDim.x) {
        int u = nlist[q / LL];
        int l = q % LL;
        long long i = (long long)u * LL + l;

        float orig = __ldg(&nodes[i]) * __ldg(&valid[i]);
        float xo, vo;
        if (level == 1) { xo = orig; vo = __ldg(&valid[i]); }
        else            { xo = g_x[i]; vo = g_v[i]; }

        float nh = g_agg[i];
        float nv = 1.0f - vo;
        float m  = sigm(nh * wf0 + xo * wf1 + nv * wf2 + b0);
        float xn = (1.0f - m) * xo + nv * m * nh;
        float vn = (l != 0 && (orig != xn || vo > 0.0f)) ? 1.0f : 0.0f;
        g_x[i] = xn;
        g_v[i] = vn;
        g_agg[i] = 0.f;                       // pre-zero for next level
        if (level == 3 && u == 0) out[l] = xn;
    }
}

extern "C" void kernel_launch(void* const* d_in, const int* in_sizes, int n_in,
                              void* d_out, int out_size) {
    const float* nodes     = (const float*)d_in[0];
    const int*   ei        = (const int*)d_in[1];
    const float* edge_attr = (const float*)d_in[2];
    const float* valid     = (const float*)d_in[3];
    const float* W1 = (const float*)d_in[6];
    const float* b1 = (const float*)d_in[7];
    const float* W2 = (const float*)d_in[8];
    const float* b2 = (const float*)d_in[9];
    const float* Wg = (const float*)d_in[10];
    const float* bg = (const float*)d_in[11];
    const float* Ww = (const float*)d_in[12];
    const float* bw = (const float*)d_in[13];
    const float* Wf = (const float*)d_in[14];
    const float* bf = (const float*)d_in[15];

    int n = in_sizes[0] / LL;
    int e = in_sizes[1] / 2;
    const int* src = ei;
    const int* dst = ei + e;
    const int tb = 256;
    int scan_blocks = (e / 8 + tb) / tb + 1;

    k_init<<<(n + tb - 1) / tb, tb>>>(n);
    k_scan_l3<<<scan_blocks, tb>>>(src, dst, e);
    k_scan_l2<<<scan_blocks, tb>>>(src, dst, e);
    k_scan_l1<<<scan_blocks, tb>>>(dst, e);
    k_zero1<<<64, tb>>>();
    k_wbase<<<148, tb>>>(edge_attr, W1, b1, W2, b2, Wg, bg, Ww, bw);

    for (int lvl = 1; lvl <= 3; lvl++) {
        k_agg<<<128, tb>>>(src, dst, nodes, valid, lvl);
        k_update<<<64, tb>>>(nodes, valid, Wf, bf, lvl, (float*)d_out);
    }
}